// round 1
// baseline (speedup 1.0000x reference)
#include <cuda_runtime.h>
#include <cuda_bf16.h>
#include <math.h>

// Problem constants
#define NB   16
#define NC   256
#define NHW  1024                 // 32*32
#define NTOK (NB * NHW)           // 16384 tokens
#define NK   8192                 // codebook size
#define NQ   (NB * NC * NHW)      // 4194304 output elements of quantized_st

// Output layout (float32): [quantized_st NQ][indices NTOK][perplexity][loss_vq][loss_commit]

// ---------------- device scratch (no allocations allowed) ----------------
__device__ float  g_cbnorm[NK];
__device__ int    g_idx[NTOK];
__device__ int    g_counts[NK];
__device__ double g_loss;

// ---------------- init: zero counts + loss ----------------
__global__ void vq_init_kernel() {
    int id = blockIdx.x * blockDim.x + threadIdx.x;
    if (id < NK) g_counts[id] = 0;
    if (id == 0) g_loss = 0.0;
}

// ---------------- codebook row norms ----------------
__global__ void vq_cbnorm_kernel(const float* __restrict__ cb) {
    // one warp per codebook row
    int warp = (blockIdx.x * blockDim.x + threadIdx.x) >> 5;
    int lane = threadIdx.x & 31;
    if (warp >= NK) return;
    const float* row = cb + (size_t)warp * NC;
    float s = 0.f;
#pragma unroll
    for (int i = 0; i < NC / 32; i++) {
        float v = row[lane + i * 32];
        s += v * v;
    }
#pragma unroll
    for (int off = 16; off; off >>= 1) s += __shfl_down_sync(0xffffffffu, s, off);
    if (lane == 0) g_cbnorm[warp] = s;
}

// ---------------- main argmin kernel ----------------
// Block: 256 threads. Tile: TM=64 tokens x all K (chunks of TK=64), C in chunks of TC=32.
// Thread (row = tid/16, col = tid%16) owns tokens {row, row+16, row+32, row+48}
// and codewords {col, col+16, col+32, col+48} within the tile -> 4x4 accumulators.
#define TM 64
#define TK 64
#define TC 32
#define ZPAD 4   // smem row stride = 36 floats (144B, 16B-aligned)

__global__ __launch_bounds__(256, 3)
void vq_argmin_kernel(const float* __restrict__ z, const float* __restrict__ cb,
                      int* __restrict__ out_idx) {
    __shared__ float zs[TM][TC + ZPAD];
    __shared__ float es[TK][TC + ZPAD];
    __shared__ float bestv[TM];
    __shared__ int   besti[TM];

    const int tid = threadIdx.x;
    const int n0  = blockIdx.x * TM;
    const int row = tid >> 4;   // 0..15
    const int col = tid & 15;   // 0..15

    if (tid < TM) { bestv[tid] = 3.4e38f; besti[tid] = 0; }

    // loading roles
    const int zt  = tid & 63;          // token within tile
    const int zcg = (tid >> 6) << 3;   // channel group base (0,8,16,24)
    const int n   = n0 + zt;
    const int zb  = n >> 10;           // batch
    const int zhw = n & 1023;          // h*32+w
    const float* zbase = z + (size_t)zb * (NC * NHW) + zhw;

    const int er = tid >> 2;           // codeword row within tile (0..63)
    const int ec = (tid & 3) << 3;     // channel offset (0,8,16,24)

    __syncthreads();

    for (int k0 = 0; k0 < NK; k0 += TK) {
        float acc[4][4];
#pragma unroll
        for (int i = 0; i < 4; i++)
#pragma unroll
            for (int j = 0; j < 4; j++) acc[i][j] = 0.f;

        for (int c0 = 0; c0 < NC; c0 += TC) {
            // load z tile: [64 tokens][32 channels]
            const float* zp = zbase + (size_t)(c0 + zcg) * NHW;
#pragma unroll
            for (int i = 0; i < 8; i++) zs[zt][zcg + i] = zp[(size_t)i * NHW];
            // load codebook tile: [64 rows][32 channels]
            const float* ep = cb + (size_t)(k0 + er) * NC + c0 + ec;
#pragma unroll
            for (int i = 0; i < 8; i++) es[er][ec + i] = ep[i];
            __syncthreads();

#pragma unroll
            for (int q = 0; q < TC / 4; q++) {
                float4 zf[4], ef[4];
#pragma unroll
                for (int i = 0; i < 4; i++)
                    zf[i] = *(const float4*)&zs[row + i * 16][q * 4];
#pragma unroll
                for (int j = 0; j < 4; j++)
                    ef[j] = *(const float4*)&es[col + j * 16][q * 4];
#pragma unroll
                for (int i = 0; i < 4; i++)
#pragma unroll
                    for (int j = 0; j < 4; j++) {
                        acc[i][j] += zf[i].x * ef[j].x;
                        acc[i][j] += zf[i].y * ef[j].y;
                        acc[i][j] += zf[i].z * ef[j].z;
                        acc[i][j] += zf[i].w * ef[j].w;
                    }
            }
            __syncthreads();
        }

        // epilogue: dist = ||e||^2 - 2*dot  (||z||^2 dropped: constant per token)
#pragma unroll
        for (int i = 0; i < 4; i++) {
            float bv = 3.4e38f;
            int   bi = -1;
#pragma unroll
            for (int j = 0; j < 4; j++) {
                int kg = k0 + col + j * 16;
                float d = g_cbnorm[kg] - 2.0f * acc[i][j];
                if (d < bv) { bv = d; bi = kg; }   // j increasing => first-occurrence kept
            }
            // reduce across the 16 lanes sharing this token (width 16, contiguous lanes)
#pragma unroll
            for (int off = 8; off; off >>= 1) {
                float ov = __shfl_down_sync(0xffffffffu, bv, off, 16);
                int   oi = __shfl_down_sync(0xffffffffu, bi, off, 16);
                if (ov < bv || (ov == bv && oi < bi)) { bv = ov; bi = oi; }
            }
            if (col == 0) {
                int t = row + i * 16;
                if (bv < bestv[t]) { bestv[t] = bv; besti[t] = bi; }
            }
        }
        // no barrier needed: bestv[t] written/read only by its owner thread across chunks;
        // zs/es rewrites are fenced by the __syncthreads at top of the c0 loop body
        __syncthreads();
    }

    if (tid < TM) out_idx[n0 + tid] = besti[tid];
}

// ---------------- writeback: quantized_st, indices, counts, loss partials ----------------
__global__ void vq_writeback_kernel(const float* __restrict__ z, const float* __restrict__ cb,
                                    const int* __restrict__ idx, float* __restrict__ out) {
    const int tid = threadIdx.x;
    const int id  = blockIdx.x * blockDim.x + tid;   // 0..NQ-1, grid covers exactly NQ

    const int b   = id >> 18;           // / (NC*NHW)
    const int rem = id & (NC * NHW - 1);
    const int c   = rem >> 10;
    const int hw  = rem & 1023;
    const int n   = (b << 10) | hw;

    const int k   = idx[n];
    const float zv = z[id];
    const float q  = cb[(size_t)k * NC + c];
    out[id] = zv + (q - zv);            // straight-through (matches z + sg(q - z))

    if (c == 0) {
        atomicAdd(&g_counts[k], 1);
        out[NQ + n] = (float)k;
    }

    float d = zv - q;
    double s = (double)d * (double)d;
#pragma unroll
    for (int off = 16; off; off >>= 1) s += __shfl_down_sync(0xffffffffu, s, off);
    __shared__ double ws[8];
    if ((tid & 31) == 0) ws[tid >> 5] = s;
    __syncthreads();
    if (tid == 0) {
        double t = 0.0;
#pragma unroll
        for (int i = 0; i < 8; i++) t += ws[i];
        atomicAdd(&g_loss, t);
    }
}

// ---------------- finalize: perplexity + losses ----------------
__global__ void vq_finalize_kernel(float* __restrict__ out) {
    const int tid = threadIdx.x;   // single block of 256
    double s = 0.0;
    for (int k = tid; k < NK; k += 256) {
        int c = g_counts[k];
        if (c > 0) {
            double p = (double)c / (double)NTOK;
            s += p * log(p);
        }
    }
#pragma unroll
    for (int off = 16; off; off >>= 1) s += __shfl_down_sync(0xffffffffu, s, off);
    __shared__ double ws[8];
    if ((tid & 31) == 0) ws[tid >> 5] = s;
    __syncthreads();
    if (tid == 0) {
        double t = 0.0;
#pragma unroll
        for (int i = 0; i < 8; i++) t += ws[i];
        float perp = (float)exp(-t);
        float loss = (float)(g_loss / (double)NQ);
        out[NQ + NTOK + 0] = perp;
        out[NQ + NTOK + 1] = loss;   // loss_vq
        out[NQ + NTOK + 2] = loss;   // loss_commit (numerically identical)
    }
}

// ---------------- launch ----------------
extern "C" void kernel_launch(void* const* d_in, const int* in_sizes, int n_in,
                              void* d_out, int out_size) {
    const float* z  = (const float*)d_in[0];
    const float* cb = (const float*)d_in[1];
    float* out = (float*)d_out;

    int* g_idx_ptr;
    cudaGetSymbolAddress((void**)&g_idx_ptr, g_idx);

    vq_init_kernel<<<NK / 256, 256>>>();
    vq_cbnorm_kernel<<<NK / 8, 256>>>(cb);                 // 8 warps/block -> 1024 blocks
    vq_argmin_kernel<<<NTOK / TM, 256>>>(z, cb, g_idx_ptr);
    vq_writeback_kernel<<<NQ / 256, 256>>>(z, cb, g_idx_ptr, out);
    vq_finalize_kernel<<<1, 256>>>(out);
}

// round 4
// speedup vs baseline: 4.8191x; 4.8191x over previous
#include <cuda_runtime.h>
#include <cuda_bf16.h>
#include <math.h>
#include <stdint.h>

// ===================== problem constants =====================
#define NB   16
#define NC   256
#define NHW  1024
#define NTOK (NB * NHW)        // 16384
#define NK   8192
#define NQ   (NB * NC * NHW)   // 4194304

#define DELTA 0.75f
#define CAND_CAP 16
#define CK_STRIDE 64

// ===================== device scratch =====================
__device__ __align__(16) uint32_t g_zfrag[(NTOK / 128) * 16384];  // 8MB, frag-order A
__device__ __align__(16) __nv_bfloat16 g_ebf[NK * NC];            // 4MB, bf16(-2e)
__device__ float  g_cbnorm[NK];
__device__ __align__(16) int g_idx[NTOK];
__device__ int    g_nc[NTOK];
__device__ int    g_ck[NTOK * CK_STRIDE];
__device__ int    g_counts[NK];
__device__ double g_loss;

__device__ __forceinline__ uint32_t smem_u32(const void* p) {
    uint32_t a;
    asm("{ .reg .u64 t; cvta.to.shared.u64 t, %1; cvt.u32.u64 %0, t; }" : "=r"(a) : "l"(p));
    return a;
}

// ===================== init =====================
__global__ void vq_init_kernel() {
    int id = blockIdx.x * blockDim.x + threadIdx.x;
    if (id < NK) g_counts[id] = 0;
    if (id == 0) g_loss = 0.0;
}

// ===================== prep z: transpose + bf16 + mma-fragment order =====================
// token n = b*1024 + hw; m = n&127; blk = n>>7. A-frag u32 at
// off = (((blk*16 + ks)*8 + mt)*32 + lane)*4 + r holds bf16 pair (k, k+1) of token row.
__global__ void vq_prep_z_kernel(const float* __restrict__ z) {
    __shared__ float t[32][33];
    int b   = blockIdx.z;
    int hw0 = blockIdx.x * 32;
    int c0  = blockIdx.y * 32;
    int lane = threadIdx.x & 31;
    int gq   = threadIdx.x >> 5;   // 0..7
    const float* zp = z + ((size_t)b * NC + c0) * NHW + hw0;
#pragma unroll
    for (int r = 0; r < 4; r++) {
        int cc = gq * 4 + r;
        t[cc][lane] = zp[(size_t)cc * NHW + lane];
    }
    __syncthreads();
#pragma unroll
    for (int it = 0; it < 2; it++) {
        int slot = threadIdx.x + it * 256;      // 0..511
        int hw_i = slot & 31;
        int cp   = slot >> 5;                   // 0..15
        int c    = c0 + 2 * cp;
        float v0 = t[2 * cp][hw_i];
        float v1 = t[2 * cp + 1][hw_i];
        uint32_t lo = (uint32_t)__bfloat16_as_ushort(__float2bfloat16(v0));
        uint32_t hi = (uint32_t)__bfloat16_as_ushort(__float2bfloat16(v1));
        uint32_t pk = lo | (hi << 16);

        int n   = b * NHW + hw0 + hw_i;
        int m   = n & 127;
        int blk = n >> 7;
        int ks  = c >> 4;
        int kk  = c & 15;
        int mt  = m >> 4;
        int m15 = m & 15;
        int g   = m15 & 7;
        int rl  = m15 >> 3;
        int tg  = (kk >> 1) & 3;
        int rh  = kk >> 3;
        int l   = g * 4 + tg;
        int r   = rl + 2 * rh;
        g_zfrag[(((blk * 16 + ks) * 8 + mt) * 32 + l) * 4 + r] = pk;
    }
}

// ===================== prep e: bf16(-2e), row-major [n][k] =====================
__global__ void vq_prep_e_kernel(const float* __restrict__ cb) {
    int id = blockIdx.x * blockDim.x + threadIdx.x;
    g_ebf[id] = __float2bfloat16(-2.0f * cb[id]);
}

// ===================== codebook row norms (exact fp32) =====================
__global__ void vq_cbnorm_kernel(const float* __restrict__ cb) {
    int warp = (blockIdx.x * blockDim.x + threadIdx.x) >> 5;
    int lane = threadIdx.x & 31;
    if (warp >= NK) return;
    const float* row = cb + (size_t)warp * NC;
    float s = 0.f;
#pragma unroll
    for (int i = 0; i < NC / 32; i++) {
        float v = row[lane + i * 32];
        s += v * v;
    }
#pragma unroll
    for (int off = 16; off; off >>= 1) s += __shfl_down_sync(0xffffffffu, s, off);
    if (lane == 0) g_cbnorm[warp] = s;
}

// ===================== main kernel: bf16 mma.sync distance + candidate capture ==========
// SMEM layout (bytes):
//   [0, 65536)        A frags (u32[16][8][32][4])
//   [65536, 86016)    B double buffer: 2 x 128 rows x 80B (32 bf16 + 8 pad)
//   [86016, 118784)   cbnorm (8192 f32)
//   [118784, 120832)  snc[8][64]
//   [120832, 153600)  scand[8][64][16]
#define SM_A     0
#define SM_B     65536
#define SM_BSTG  10240
#define SM_CBN   86016
#define SM_SNC   118784
#define SM_SCAND 120832
#define SM_TOTAL 153600

__global__ void __launch_bounds__(256, 1) vq_argmin_mma_kernel() {
    extern __shared__ char smem[];
    uint32_t sb = smem_u32(smem);
    const int tid  = threadIdx.x;
    const int wid  = tid >> 5;
    const int lane = tid & 31;
    const int wm   = wid >> 2;       // 0..1
    const int wn   = wid & 3;        // 0..3
    const int g    = lane >> 2;      // 0..7
    const int tg   = lane & 3;       // 0..3
    const int blk  = blockIdx.x;
    const int n_base = blk * 128;

    uint4*  Asm   = (uint4*)(smem + SM_A);
    float*  cbn   = (float*)(smem + SM_CBN);
    int*    snc   = (int*)(smem + SM_SNC);          // [8][64]
    int*    scand = (int*)(smem + SM_SCAND);        // [8][64][16]

    // ---- stage A frags + cbnorm, zero counters ----
    {
        const uint4* src = (const uint4*)(g_zfrag + (size_t)blk * 16384);
#pragma unroll
        for (int i = 0; i < 16; i++) Asm[tid + i * 256] = src[tid + i * 256];
        const float4* cs = (const float4*)g_cbnorm;
        float4* cd = (float4*)cbn;
#pragma unroll
        for (int i = 0; i < 8; i++) cd[tid + i * 256] = cs[tid + i * 256];
        snc[tid] = 0;
        snc[tid + 256] = 0;
    }
    __syncthreads();

    // ---- cp.async B loader ----
    const int ln   = tid >> 1;        // row 0..127
    const int lh   = tid & 1;         // k-half
    // prologue: chunk 0 (each thread: 32 contiguous bytes = 16 bf16 at k offset lh*16)
    {
        const char* src = (const char*)(g_ebf) + ((size_t)ln * 256 + lh * 16) * 2;
        uint32_t dst = sb + SM_B + ln * 80 + lh * 32;
        asm volatile("cp.async.cg.shared.global [%0], [%1], 16;" :: "r"(dst), "l"(src));
        asm volatile("cp.async.cg.shared.global [%0], [%1], 16;" :: "r"(dst + 16), "l"(src + 16));
        asm volatile("cp.async.commit_group;" ::: "memory");
    }

    float acc[4][4][4];
    float minv[8];
#pragma unroll
    for (int i = 0; i < 8; i++) minv[i] = 3.4e38f;

    // ldmatrix source addresses (fixed within buffer)
    const int rowsel = lane >> 4;             // 0/1
    const int kbsel  = ((lane >> 3) & 1) * 16;
    const uint32_t bA1 = (uint32_t)(((wn * 4 + rowsel) * 8 + (lane & 7)) * 80 + kbsel);
    const uint32_t bA2 = (uint32_t)(((wn * 4 + 2 + rowsel) * 8 + (lane & 7)) * 80 + kbsel);

    for (int T = 0; T < 512; T++) {
        const int tile = T >> 3;
        const int c    = T & 7;

        asm volatile("cp.async.wait_group 0;" ::: "memory");
        __syncthreads();

        if (T + 1 < 512) {
            const int Tn = T + 1;
            const char* src = (const char*)(g_ebf) +
                ((size_t)((Tn >> 3) * 128 + ln) * 256 + (Tn & 7) * 32 + lh * 16) * 2;
            uint32_t dst = sb + SM_B + ((Tn & 1) * SM_BSTG) + ln * 80 + lh * 32;
            asm volatile("cp.async.cg.shared.global [%0], [%1], 16;" :: "r"(dst), "l"(src));
            asm volatile("cp.async.cg.shared.global [%0], [%1], 16;" :: "r"(dst + 16), "l"(src + 16));
            asm volatile("cp.async.commit_group;" ::: "memory");
        }

        if (c == 0) {
#pragma unroll
            for (int m = 0; m < 4; m++)
#pragma unroll
                for (int j = 0; j < 4; j++)
#pragma unroll
                    for (int r = 0; r < 4; r++) acc[m][j][r] = 0.f;
        }

        const uint32_t bbase = sb + SM_B + (T & 1) * SM_BSTG;
#pragma unroll
        for (int s2 = 0; s2 < 2; s2++) {
            const int ks = c * 2 + s2;
            uint32_t a[4][4];
#pragma unroll
            for (int m2 = 0; m2 < 4; m2++) {
                uint4 v = Asm[(ks * 8 + (wm * 4 + m2)) * 32 + lane];
                a[m2][0] = v.x; a[m2][1] = v.y; a[m2][2] = v.z; a[m2][3] = v.w;
            }
            uint32_t b[4][2];
            asm volatile("ldmatrix.sync.aligned.m8n8.x4.shared.b16 {%0,%1,%2,%3}, [%4];"
                : "=r"(b[0][0]), "=r"(b[0][1]), "=r"(b[1][0]), "=r"(b[1][1])
                : "r"(bbase + bA1 + s2 * 32));
            asm volatile("ldmatrix.sync.aligned.m8n8.x4.shared.b16 {%0,%1,%2,%3}, [%4];"
                : "=r"(b[2][0]), "=r"(b[2][1]), "=r"(b[3][0]), "=r"(b[3][1])
                : "r"(bbase + bA2 + s2 * 32));
#pragma unroll
            for (int m2 = 0; m2 < 4; m2++)
#pragma unroll
                for (int j = 0; j < 4; j++) {
                    asm volatile(
                        "mma.sync.aligned.m16n8k16.row.col.f32.bf16.bf16.f32 "
                        "{%0,%1,%2,%3}, {%4,%5,%6,%7}, {%8,%9}, {%0,%1,%2,%3};"
                        : "+f"(acc[m2][j][0]), "+f"(acc[m2][j][1]),
                          "+f"(acc[m2][j][2]), "+f"(acc[m2][j][3])
                        : "r"(a[m2][0]), "r"(a[m2][1]), "r"(a[m2][2]), "r"(a[m2][3]),
                          "r"(b[j][0]), "r"(b[j][1]));
                }
        }

        if (c == 7) {
            // -------- per-tile epilogue --------
            const int nb = tile * 128 + wn * 32;
            float2 cb2[4];
#pragma unroll
            for (int j = 0; j < 4; j++)
                cb2[j] = *(const float2*)(cbn + nb + j * 8 + 2 * tg);
#pragma unroll
            for (int mh = 0; mh < 8; mh++) {
                const int m = mh >> 1, h = mh & 1;
                float d0[8];
#pragma unroll
                for (int j = 0; j < 4; j++) {
                    d0[2 * j]     = acc[m][j][2 * h]     + cb2[j].x;
                    d0[2 * j + 1] = acc[m][j][2 * h + 1] + cb2[j].y;
                }
                float lm = d0[0];
#pragma unroll
                for (int i = 1; i < 8; i++) lm = fminf(lm, d0[i]);
                lm = fminf(lm, __shfl_xor_sync(0xffffffffu, lm, 1));
                lm = fminf(lm, __shfl_xor_sync(0xffffffffu, lm, 2));
                if (lm < minv[mh] + DELTA) {
                    const float thr2 = fminf(minv[mh], lm) + DELTA;
                    const int tl = m * 16 + h * 8 + g;
#pragma unroll
                    for (int j = 0; j < 4; j++)
#pragma unroll
                        for (int p = 0; p < 2; p++) {
                            float d = d0[2 * j + p];
                            if (d < thr2) {
                                int slot = atomicAdd(&snc[wid * 64 + tl], 1);
                                if (slot < CAND_CAP)
                                    scand[(wid * 64 + tl) * CAND_CAP + slot] =
                                        nb + j * 8 + 2 * tg + p;
                            }
                        }
                    minv[mh] = fminf(minv[mh], lm);
                }
            }
        }
    }

    __syncthreads();
    // -------- merge 4 N-warps per token --------
    if (tid < 128) {
        const int wmg = tid >> 6, tl = tid & 63;
        const int tok = n_base + tid;
        int total = 0;
        bool ovf = false;
        for (int w = wmg * 4; w < wmg * 4 + 4; w++) {
            int cnum = snc[w * 64 + tl];
            if (cnum > CAND_CAP) { ovf = true; cnum = CAND_CAP; }
            for (int s = 0; s < cnum; s++)
                g_ck[tok * CK_STRIDE + total + s] = scand[(w * 64 + tl) * CAND_CAP + s];
            total += cnum;
        }
        g_nc[tok] = ovf ? 255 : total;
    }
}

// ===================== exact rescoring =====================
__device__ __forceinline__ float vq_exact_dist(const float* __restrict__ cb,
                                               const float zr[8], int k, int lane) {
    const float* cr = cb + (size_t)k * NC + lane;
    float s = 0.f;
#pragma unroll
    for (int u = 0; u < 8; u++) s += zr[u] * cr[u * 32];
#pragma unroll
    for (int off = 16; off; off >>= 1) s += __shfl_xor_sync(0xffffffffu, s, off);
    return g_cbnorm[k] - 2.0f * s;
}

__global__ void vq_rescore_kernel(const float* __restrict__ z, const float* __restrict__ cb) {
    int n = (blockIdx.x * blockDim.x + threadIdx.x) >> 5;
    int lane = threadIdx.x & 31;
    if (n >= NTOK) return;
    int nc = g_nc[n];

    int b = n >> 10, hw = n & 1023;
    const float* zp = z + (size_t)b * NC * NHW + hw;
    float zr[8];
#pragma unroll
    for (int u = 0; u < 8; u++) zr[u] = zp[(size_t)(lane + u * 32) * NHW];

    float bd = 3.4e38f;
    int bk = 0x7fffffff;
    if (nc < 255) {
        for (int i = 0; i < nc; i++) {
            int k = g_ck[n * CK_STRIDE + i];
            float d = vq_exact_dist(cb, zr, k, lane);
            if (d < bd || (d == bd && k < bk)) { bd = d; bk = k; }
        }
    } else {
        for (int k = 0; k < NK; k++) {
            float d = vq_exact_dist(cb, zr, k, lane);
            if (d < bd || (d == bd && k < bk)) { bd = d; bk = k; }
        }
    }
    if (lane == 0) g_idx[n] = bk;
}

// ===================== writeback =====================
__global__ void vq_writeback_kernel(const float* __restrict__ z, const float* __restrict__ cb,
                                    float* __restrict__ out) {
    const int tid = threadIdx.x;
    const int id = (blockIdx.x * 256 + tid) * 4;

    const int b   = id >> 18;
    const int rem = id & (NC * NHW - 1);
    const int c   = rem >> 10;
    const int hw0 = rem & 1023;
    const int nb  = (b << 10) | hw0;

    int4 kk = *(const int4*)(g_idx + nb);
    float4 zv = *(const float4*)(z + id);
    float4 q;
    q.x = cb[(size_t)kk.x * NC + c];
    q.y = cb[(size_t)kk.y * NC + c];
    q.z = cb[(size_t)kk.z * NC + c];
    q.w = cb[(size_t)kk.w * NC + c];

    float4 o;
    o.x = zv.x + (q.x - zv.x);
    o.y = zv.y + (q.y - zv.y);
    o.z = zv.z + (q.z - zv.z);
    o.w = zv.w + (q.w - zv.w);
    *(float4*)(out + id) = o;

    if (c == 0) {
        atomicAdd(&g_counts[kk.x], 1);
        atomicAdd(&g_counts[kk.y], 1);
        atomicAdd(&g_counts[kk.z], 1);
        atomicAdd(&g_counts[kk.w], 1);
        float4 fi = make_float4((float)kk.x, (float)kk.y, (float)kk.z, (float)kk.w);
        *(float4*)(out + NQ + nb) = fi;
    }

    float dx = zv.x - q.x, dy = zv.y - q.y, dz = zv.z - q.z, dw = zv.w - q.w;
    double s = (double)dx * dx + (double)dy * dy + (double)dz * dz + (double)dw * dw;
#pragma unroll
    for (int off = 16; off; off >>= 1) s += __shfl_down_sync(0xffffffffu, s, off);
    __shared__ double ws[8];
    if ((tid & 31) == 0) ws[tid >> 5] = s;
    __syncthreads();
    if (tid == 0) {
        double t = 0.0;
#pragma unroll
        for (int i = 0; i < 8; i++) t += ws[i];
        atomicAdd(&g_loss, t);
    }
}

// ===================== finalize =====================
__global__ void vq_finalize_kernel(float* __restrict__ out) {
    const int tid = threadIdx.x;
    double s = 0.0;
    for (int k = tid; k < NK; k += 256) {
        int c = g_counts[k];
        if (c > 0) {
            double p = (double)c / (double)NTOK;
            s += p * log(p);
        }
    }
#pragma unroll
    for (int off = 16; off; off >>= 1) s += __shfl_down_sync(0xffffffffu, s, off);
    __shared__ double ws[8];
    if ((tid & 31) == 0) ws[tid >> 5] = s;
    __syncthreads();
    if (tid == 0) {
        double t = 0.0;
#pragma unroll
        for (int i = 0; i < 8; i++) t += ws[i];
        float perp = (float)exp(-t);
        float loss = (float)(g_loss / (double)NQ);
        out[NQ + NTOK + 0] = perp;
        out[NQ + NTOK + 1] = loss;
        out[NQ + NTOK + 2] = loss;
    }
}

// ===================== launch =====================
extern "C" void kernel_launch(void* const* d_in, const int* in_sizes, int n_in,
                              void* d_out, int out_size) {
    const float* z  = (const float*)d_in[0];
    const float* cb = (const float*)d_in[1];
    float* out = (float*)d_out;

    static bool attr_set = false;
    if (!attr_set) {
        cudaFuncSetAttribute(vq_argmin_mma_kernel,
                             cudaFuncAttributeMaxDynamicSharedMemorySize, SM_TOTAL);
        attr_set = true;
    }

    vq_init_kernel<<<NK / 256, 256>>>();
    vq_prep_z_kernel<<<dim3(32, 8, 16), 256>>>(z);
    vq_prep_e_kernel<<<(NK * NC) / 256, 256>>>(cb);
    vq_cbnorm_kernel<<<NK / 8, 256>>>(cb);
    vq_argmin_mma_kernel<<<NTOK / 128, 256, SM_TOTAL>>>();
    vq_rescore_kernel<<<NTOK / 8, 256>>>(z, cb);
    vq_writeback_kernel<<<NQ / 1024, 256>>>(z, cb, out);
    vq_finalize_kernel<<<1, 256>>>(out);
}